// round 8
// baseline (speedup 1.0000x reference)
#include <cuda_runtime.h>

// QLSTM collapsed analytically:
//   quantum_gate(comb, p)[:, k] = prod_{j<=k} cos(p_j) * cos(comb_j)
// Only k < H=4 used; comb[0:4] = x  => gates depend only on x_t.
// Per (b,k): c = f*c + i*g ; h = o*tanh(c); gate args in [-1,1], |c| <= 1.25.
//
// Mapping (round 7 layout): warp = 2 batch els x HALF of T (64 steps);
//   lane = (chunk 0..15)*2 + bsub(0..1); chunk = 4 steps; 4096 warps.
// NEW: all per-k math packed 2-wide in f32x2 (k01 / k23 pairs) via PTX
//   fma.rn.f32x2 / mul.rn.f32x2 / add.rn.f32x2 — halves FMA-pipe instrs.
// Pass 1: load x once, cache packed f, i*g, o; chunk affine aggregates.
// Warp scan (packed) + smem half-link. Pass 2: register-only recurrence.

#define T_STEPS 128
#define BATCH   4096
#define CHUNK   4
#define FULLMASK 0xffffffffu

typedef unsigned long long ull;

__device__ __forceinline__ ull pack2(float lo, float hi) {
    ull r; asm("mov.b64 %0, {%1, %2};" : "=l"(r) : "f"(lo), "f"(hi)); return r;
}
__device__ __forceinline__ float2 unpack2(ull v) {
    float2 r; asm("mov.b64 {%0, %1}, %2;" : "=f"(r.x), "=f"(r.y) : "l"(v)); return r;
}
__device__ __forceinline__ ull fma2(ull a, ull b, ull c) {
    ull d; asm("fma.rn.f32x2 %0, %1, %2, %3;" : "=l"(d) : "l"(a), "l"(b), "l"(c)); return d;
}
__device__ __forceinline__ ull mul2(ull a, ull b) {
    ull d; asm("mul.rn.f32x2 %0, %1, %2;" : "=l"(d) : "l"(a), "l"(b)); return d;
}
__device__ __forceinline__ ull add2(ull a, ull b) {
    ull d; asm("add.rn.f32x2 %0, %1, %2;" : "=l"(d) : "l"(a), "l"(b)); return d;
}
__device__ __forceinline__ float rcpa(float x) {
    float r; asm("rcp.approx.f32 %0, %1;" : "=f"(r) : "f"(x)); return r;
}
__device__ __forceinline__ ull rcp2(ull v) {
    float2 t = unpack2(v);
    return pack2(rcpa(t.x), rcpa(t.y));
}

__global__ void __launch_bounds__(128, 5) qlstm_kernel(
    const float* __restrict__ inp,   // [T, B, 4]
    const float* __restrict__ prm_f, // [8]
    const float* __restrict__ prm_i,
    const float* __restrict__ prm_g,
    const float* __restrict__ prm_o,
    float* __restrict__ out)         // [T*B*4 + B*4 + B*4]
{
    const int wid   = threadIdx.x >> 5;      // 0..3
    const int lane  = threadIdx.x & 31;
    const int half  = wid & 1;               // t-half
    const int pair  = wid >> 1;              // b-pair within block
    const int bsub  = lane & 1;
    const int chunk = lane >> 1;             // 0..15
    const int b     = blockIdx.x * 4 + pair * 2 + bsub;
    const int t0    = half * 64 + chunk * CHUNK;

    __shared__ ull sC[2][2][2];   // [pair][bsub][k01/k23] : half-0 total c @t=63

    // packed sigmoid coefficients (sigmoid(2u) = 0.5 + u*q(u^2), deg-9 Taylor)
    const ull C9 = pack2( 0.010934744f,  0.010934744f);
    const ull C7 = pack2(-0.026984127f, -0.026984127f);
    const ull C5 = pack2( 0.066666667f,  0.066666667f);
    const ull C3 = pack2(-0.166666667f, -0.166666667f);
    const ull CH = pack2( 0.5f,          0.5f);
    // tanh Pade(5,4) constants: z(w^2+105w+945) / (15w^2+420w+945)
    const ull K105 = pack2(105.f, 105.f), K945 = pack2(945.f, 945.f);
    const ull K420 = pack2(420.f, 420.f), K15  = pack2(15.f, 15.f);

    // per-k parameter prefix products, packed (k0,k1) / (k2,k3)
    ull AFh01, AFh23, AIh01, AIh23, AG01, AG23, AOh01, AOh23;
    {
        float pf_ = 1.f, pi_ = 1.f, pg_ = 1.f, po_ = 1.f;
        float af[4], ai[4], ag[4], ao[4];
#pragma unroll
        for (int j = 0; j < 4; ++j) {
            pf_ *= __cosf(prm_f[j]);
            pi_ *= __cosf(prm_i[j]);
            pg_ *= __cosf(prm_g[j]);
            po_ *= __cosf(prm_o[j]);
            af[j] = 0.5f * pf_;   // sigmoid poly takes arg/2
            ai[j] = 0.5f * pi_;
            ag[j] = pg_;
            ao[j] = 0.5f * po_;
        }
        AFh01 = pack2(af[0], af[1]); AFh23 = pack2(af[2], af[3]);
        AIh01 = pack2(ai[0], ai[1]); AIh23 = pack2(ai[2], ai[3]);
        AG01  = pack2(ag[0], ag[1]); AG23  = pack2(ag[2], ag[3]);
        AOh01 = pack2(ao[0], ao[1]); AOh23 = pack2(ao[2], ao[3]);
    }

    // packed sigmoid / tanh helpers (lambdas to capture consts)
    auto sig2 = [&](ull u) -> ull {
        ull w = mul2(u, u);
        ull q = fma2(w, fma2(w, fma2(w, fma2(w, C9, C7), C5), C3), CH);
        return fma2(u, q, CH);
    };
    auto tanh54_2 = [&](ull z) -> ull {
        ull w = mul2(z, z);
        ull n = mul2(z, fma2(w, add2(w, K105), K945));
        ull d = fma2(w, fma2(w, K15, K420), K945);
        return mul2(n, rcp2(d));
    };

    const float4* __restrict__ xin = (const float4*)inp;

    // ---- pass 1: load once, compute + cache packed gates, chunk aggregates ----
    ull Fc01[CHUNK], Fc23[CHUNK], Gc01[CHUNK], Gc23[CHUNK], Oc01[CHUNK], Oc23[CHUNK];
    ull cl01 = 0, cl23 = 0;                         // packed (0,0)
    ull pf01 = pack2(1.f, 1.f), pf23 = pf01;

#pragma unroll
    for (int it = 0; it < CHUNK; ++it) {
        float4 x = xin[(t0 + it) * BATCH + b];
        float P0 = __cosf(x.x);
        float P1 = P0 * __cosf(x.y);
        float P2 = P1 * __cosf(x.z);
        float P3 = P2 * __cosf(x.w);
        ull P01 = pack2(P0, P1), P23 = pack2(P2, P3);

        ull f01 = sig2(mul2(AFh01, P01)), f23 = sig2(mul2(AFh23, P23));
        ull i01 = sig2(mul2(AIh01, P01)), i23 = sig2(mul2(AIh23, P23));
        ull g01 = tanh54_2(mul2(AG01, P01)), g23 = tanh54_2(mul2(AG23, P23));
        ull o01 = sig2(mul2(AOh01, P01)), o23 = sig2(mul2(AOh23, P23));

        ull ig01 = mul2(i01, g01), ig23 = mul2(i23, g23);
        Fc01[it] = f01; Fc23[it] = f23;
        Gc01[it] = ig01; Gc23[it] = ig23;
        Oc01[it] = o01; Oc23[it] = o23;

        cl01 = fma2(f01, cl01, ig01);
        cl23 = fma2(f23, cl23, ig23);
        pf01 = mul2(pf01, f01);
        pf23 = mul2(pf23, f23);
    }

    // ---- packed scan over 16 chunks (lanes stride 2, same bsub) ----
    ull F01 = pf01, C01 = cl01, F23 = pf23, C23 = cl23;
#pragma unroll
    for (int off = 1; off <= 8; off <<= 1) {
        const int ol = off * 2;
        ull Fo01 = __shfl_up_sync(FULLMASK, F01, ol);
        ull Co01 = __shfl_up_sync(FULLMASK, C01, ol);
        ull Fo23 = __shfl_up_sync(FULLMASK, F23, ol);
        ull Co23 = __shfl_up_sync(FULLMASK, C23, ol);
        if (chunk >= off) {
            C01 = fma2(F01, Co01, C01); F01 = mul2(F01, Fo01);
            C23 = fma2(F23, Co23, C23); F23 = mul2(F23, Fo23);
        }
    }

    // half-0 publishes total c at t=63
    if (half == 0 && chunk == 15) {
        sC[pair][bsub][0] = C01;
        sC[pair][bsub][1] = C23;
    }

    // exclusive prefix within this half
    ull Fe01 = __shfl_up_sync(FULLMASK, F01, 2);
    ull Ce01 = __shfl_up_sync(FULLMASK, C01, 2);
    ull Fe23 = __shfl_up_sync(FULLMASK, F23, 2);
    ull Ce23 = __shfl_up_sync(FULLMASK, C23, 2);
    if (chunk == 0) {
        Fe01 = pack2(1.f, 1.f); Ce01 = 0;
        Fe23 = pack2(1.f, 1.f); Ce23 = 0;
    }

    __syncthreads();

    ull ch01 = 0, ch23 = 0;
    if (half == 1) {
        ch01 = sC[pair][bsub][0];
        ch23 = sC[pair][bsub][1];
    }
    ull c01 = fma2(Fe01, ch01, Ce01);
    ull c23 = fma2(Fe23, ch23, Ce23);

    // ---- pass 2: register-only recurrence, emit h ----
    // tanh Pade(7,6) packed: |c| <= 1.25 here, err < 1e-7
    const ull K21    = pack2(21.f, 21.f),     K1260 = pack2(1260.f, 1260.f);
    const ull K10395 = pack2(10395.f, 10395.f);
    const ull K210   = pack2(210.f, 210.f),   K4725 = pack2(4725.f, 4725.f);
    auto tanh76_2 = [&](ull z) -> ull {
        ull w = mul2(z, z);
        ull n = mul2(z, fma2(w, fma2(w, K21, K1260), K10395));
        ull d = fma2(w, fma2(w, add2(w, K210), K4725), K10395);
        return mul2(n, rcp2(d));
    };

    float4* __restrict__ out4 = (float4*)out;
    ull h01 = 0, h23 = 0;

#pragma unroll
    for (int it = 0; it < CHUNK; ++it) {
        c01 = fma2(Fc01[it], c01, Gc01[it]);
        c23 = fma2(Fc23[it], c23, Gc23[it]);

        h01 = mul2(Oc01[it], tanh76_2(c01));
        h23 = mul2(Oc23[it], tanh76_2(c23));

        float2 a = unpack2(h01), c_ = unpack2(h23);
        __stcs(&out4[(t0 + it) * BATCH + b], make_float4(a.x, a.y, c_.x, c_.y));
    }

    // final state from half 1, chunk 15, it=3 (t = 127)
    if (half == 1 && chunk == 15) {
        float2 ha = unpack2(h01), hb = unpack2(h23);
        float2 ca = unpack2(c01), cb = unpack2(c23);
        out4[T_STEPS * BATCH + b]         = make_float4(ha.x, ha.y, hb.x, hb.y); // hx
        out4[T_STEPS * BATCH + BATCH + b] = make_float4(ca.x, ca.y, cb.x, cb.y); // cx
    }
}

extern "C" void kernel_launch(void* const* d_in, const int* in_sizes, int n_in,
                              void* d_out, int out_size) {
    (void)in_sizes; (void)n_in; (void)out_size;
    const float* inp   = (const float*)d_in[0];
    const float* prm_f = (const float*)d_in[1];
    const float* prm_i = (const float*)d_in[2];
    const float* prm_g = (const float*)d_in[3];
    const float* prm_o = (const float*)d_in[4];
    float* out = (float*)d_out;

    // 4096 warps: 2 b x half-T per warp; 4 warps/block -> 1024 blocks
    qlstm_kernel<<<1024, 128>>>(inp, prm_f, prm_i, prm_g, prm_o, out);
}

// round 9
// speedup vs baseline: 1.0239x; 1.0239x over previous
#include <cuda_runtime.h>

// QLSTM collapsed analytically:
//   quantum_gate(comb, p)[:, k] = prod_{j<=k} cos(p_j) * cos(comb_j)
// Only k < H=4 used; comb[0:4] = x  => gates depend only on x_t.
// Per (b,k): c = f*c + i*g ; h = o*tanh(c); gate args in [-1,1], |c| <= 2.1.
//
// Mapping: warp = 2 batch els x QUARTER of T (32 steps); CHUNK=2.
//   lane = (chunk 0..15)*2 + bsub(0..1). Block = 4 warps = 4 quarters of one
//   b-pair. 8192 warps total -> ~50% occupancy at <=64 regs.
// Pass 1: load x once, cache f, i*g, o (24 floats); chunk affine aggregates.
// Warp scan (4 rounds) over 16 chunks; quarters linked via smem affine fold.
// Pass 2: pure-register recurrence + streaming stores. No reloads.

#define T_STEPS 128
#define BATCH   4096
#define CHUNK   2
#define FULLMASK 0xffffffffu

// sigmoid(2u), |u|<=0.5 : 0.5 + u*q(u^2); tanh Taylor deg-9 halved, err ~2e-6
__device__ __forceinline__ float sig_poly(float u) {
    float w = u * u;
    float q = fmaf(w, fmaf(w, fmaf(w, fmaf(w, 0.010934744f,
                                              -0.026984127f),
                                       0.066666667f),
                               -0.166666667f),
                       0.5f);
    return fmaf(u, q, 0.5f);
}
// tanh Pade(5,4); |z|<=1, err ~4e-8
__device__ __forceinline__ float tanh_p54(float z) {
    float w = z * z;
    float n = z * fmaf(w, fmaf(w, 1.0f, 105.0f), 945.0f);
    float d =     fmaf(w, fmaf(w, 15.0f, 420.0f), 945.0f);
    return __fdividef(n, d);
}
// tanh Pade(7,6); |z|<=2.5, err ~1e-6
__device__ __forceinline__ float tanh_p76(float z) {
    float w = z * z;
    float n = z * fmaf(w, fmaf(w, 21.0f, 1260.0f), 10395.0f);
    float d =     fmaf(w, fmaf(w, fmaf(w, 1.0f, 210.0f), 4725.0f), 10395.0f);
    return __fdividef(n, d);
}

__global__ void __launch_bounds__(128, 8) qlstm_kernel(
    const float* __restrict__ inp,   // [T, B, 4]
    const float* __restrict__ prm_f, // [8]
    const float* __restrict__ prm_i,
    const float* __restrict__ prm_g,
    const float* __restrict__ prm_o,
    float* __restrict__ out)         // [T*B*4 + B*4 + B*4]
{
    const int quarter = threadIdx.x >> 5;    // 0..3 : which quarter of T
    const int lane    = threadIdx.x & 31;
    const int bsub    = lane & 1;
    const int chunk   = lane >> 1;           // 0..15
    const int b       = blockIdx.x * 2 + bsub;
    const int t0      = quarter * 32 + chunk * CHUNK;

    // quarter totals: affine map (F_tot, C_tot) per (quarter, bsub, k0..3)
    __shared__ float4 sF[4][2];
    __shared__ float4 sC[4][2];

    // per-k parameter prefix products (uniform)
    float AFh[4], AIh[4], AG[4], AOh[4];
    {
        float pf_ = 1.0f, pi_ = 1.0f, pg_ = 1.0f, po_ = 1.0f;
#pragma unroll
        for (int j = 0; j < 4; ++j) {
            pf_ *= __cosf(prm_f[j]);
            pi_ *= __cosf(prm_i[j]);
            pg_ *= __cosf(prm_g[j]);
            po_ *= __cosf(prm_o[j]);
            AFh[j] = 0.5f * pf_;   // sigmoid poly takes arg/2
            AIh[j] = 0.5f * pi_;
            AG[j]  = pg_;
            AOh[j] = 0.5f * po_;
        }
    }

    const float4* __restrict__ xin = (const float4*)inp;

    // ---- pass 1: load once, cache gates, accumulate chunk affine map ----
    float Fc[CHUNK][4], Gc[CHUNK][4], Oc[CHUNK][4];
    float cl0 = 0.f, cl1 = 0.f, cl2 = 0.f, cl3 = 0.f;
    float pf0 = 1.f, pf1 = 1.f, pf2 = 1.f, pf3 = 1.f;

#pragma unroll
    for (int it = 0; it < CHUNK; ++it) {
        float4 x = xin[(t0 + it) * BATCH + b];
        float P0 = __cosf(x.x);
        float P1 = P0 * __cosf(x.y);
        float P2 = P1 * __cosf(x.z);
        float P3 = P2 * __cosf(x.w);

        float f, i, g, ig;
        f = sig_poly(AFh[0] * P0); i = sig_poly(AIh[0] * P0); g = tanh_p54(AG[0] * P0);
        ig = i * g; Fc[it][0] = f; Gc[it][0] = ig; Oc[it][0] = sig_poly(AOh[0] * P0);
        cl0 = fmaf(f, cl0, ig); pf0 *= f;

        f = sig_poly(AFh[1] * P1); i = sig_poly(AIh[1] * P1); g = tanh_p54(AG[1] * P1);
        ig = i * g; Fc[it][1] = f; Gc[it][1] = ig; Oc[it][1] = sig_poly(AOh[1] * P1);
        cl1 = fmaf(f, cl1, ig); pf1 *= f;

        f = sig_poly(AFh[2] * P2); i = sig_poly(AIh[2] * P2); g = tanh_p54(AG[2] * P2);
        ig = i * g; Fc[it][2] = f; Gc[it][2] = ig; Oc[it][2] = sig_poly(AOh[2] * P2);
        cl2 = fmaf(f, cl2, ig); pf2 *= f;

        f = sig_poly(AFh[3] * P3); i = sig_poly(AIh[3] * P3); g = tanh_p54(AG[3] * P3);
        ig = i * g; Fc[it][3] = f; Gc[it][3] = ig; Oc[it][3] = sig_poly(AOh[3] * P3);
        cl3 = fmaf(f, cl3, ig); pf3 *= f;
    }

    // ---- scan over 16 chunks (lanes stride 2, same bsub) ----
    float F0 = pf0, C0 = cl0, F1 = pf1, C1 = cl1;
    float F2 = pf2, C2 = cl2, F3 = pf3, C3 = cl3;
#pragma unroll
    for (int off = 1; off <= 8; off <<= 1) {
        const int ol = off * 2;
        float Fo0 = __shfl_up_sync(FULLMASK, F0, ol), Co0 = __shfl_up_sync(FULLMASK, C0, ol);
        float Fo1 = __shfl_up_sync(FULLMASK, F1, ol), Co1 = __shfl_up_sync(FULLMASK, C1, ol);
        float Fo2 = __shfl_up_sync(FULLMASK, F2, ol), Co2 = __shfl_up_sync(FULLMASK, C2, ol);
        float Fo3 = __shfl_up_sync(FULLMASK, F3, ol), Co3 = __shfl_up_sync(FULLMASK, C3, ol);
        if (chunk >= off) {
            C0 = fmaf(F0, Co0, C0); F0 *= Fo0;
            C1 = fmaf(F1, Co1, C1); F1 *= Fo1;
            C2 = fmaf(F2, Co2, C2); F2 *= Fo2;
            C3 = fmaf(F3, Co3, C3); F3 *= Fo3;
        }
    }

    // publish this quarter's total affine map (chunk 15 inclusive values)
    if (chunk == 15) {
        sF[quarter][bsub] = make_float4(F0, F1, F2, F3);
        sC[quarter][bsub] = make_float4(C0, C1, C2, C3);
    }

    // exclusive prefix within this quarter
    float Fe0 = __shfl_up_sync(FULLMASK, F0, 2), Ce0 = __shfl_up_sync(FULLMASK, C0, 2);
    float Fe1 = __shfl_up_sync(FULLMASK, F1, 2), Ce1 = __shfl_up_sync(FULLMASK, C1, 2);
    float Fe2 = __shfl_up_sync(FULLMASK, F2, 2), Ce2 = __shfl_up_sync(FULLMASK, C2, 2);
    float Fe3 = __shfl_up_sync(FULLMASK, F3, 2), Ce3 = __shfl_up_sync(FULLMASK, C3, 2);
    if (chunk == 0) {
        Fe0 = 1.f; Ce0 = 0.f; Fe1 = 1.f; Ce1 = 0.f;
        Fe2 = 1.f; Ce2 = 0.f; Fe3 = 1.f; Ce3 = 0.f;
    }

    __syncthreads();

    // fold preceding quarters' maps: c = C_q + F_q * c, q = 0..quarter-1
    float ch0 = 0.f, ch1 = 0.f, ch2 = 0.f, ch3 = 0.f;
#pragma unroll
    for (int q = 0; q < 3; ++q) {
        if (quarter > q) {
            float4 Fq = sF[q][bsub];
            float4 Cq = sC[q][bsub];
            ch0 = fmaf(Fq.x, ch0, Cq.x);
            ch1 = fmaf(Fq.y, ch1, Cq.y);
            ch2 = fmaf(Fq.z, ch2, Cq.z);
            ch3 = fmaf(Fq.w, ch3, Cq.w);
        }
    }

    float c0 = fmaf(Fe0, ch0, Ce0);
    float c1 = fmaf(Fe1, ch1, Ce1);
    float c2 = fmaf(Fe2, ch2, Ce2);
    float c3 = fmaf(Fe3, ch3, Ce3);

    // ---- pass 2: pure-register recurrence, emit h ----
    float4* __restrict__ out4 = (float4*)out;
    float h0 = 0.f, h1 = 0.f, h2 = 0.f, h3 = 0.f;

#pragma unroll
    for (int it = 0; it < CHUNK; ++it) {
        c0 = fmaf(Fc[it][0], c0, Gc[it][0]);
        c1 = fmaf(Fc[it][1], c1, Gc[it][1]);
        c2 = fmaf(Fc[it][2], c2, Gc[it][2]);
        c3 = fmaf(Fc[it][3], c3, Gc[it][3]);

        h0 = Oc[it][0] * tanh_p76(c0);
        h1 = Oc[it][1] * tanh_p76(c1);
        h2 = Oc[it][2] * tanh_p76(c2);
        h3 = Oc[it][3] * tanh_p76(c3);

        __stcs(&out4[(t0 + it) * BATCH + b], make_float4(h0, h1, h2, h3));
    }

    // final state: quarter 3, chunk 15, it = CHUNK-1 (t = 127)
    if (quarter == 3 && chunk == 15) {
        out4[T_STEPS * BATCH + b]         = make_float4(h0, h1, h2, h3); // hx
        out4[T_STEPS * BATCH + BATCH + b] = make_float4(c0, c1, c2, c3); // cx
    }
}

extern "C" void kernel_launch(void* const* d_in, const int* in_sizes, int n_in,
                              void* d_out, int out_size) {
    (void)in_sizes; (void)n_in; (void)out_size;
    const float* inp   = (const float*)d_in[0];
    const float* prm_f = (const float*)d_in[1];
    const float* prm_i = (const float*)d_in[2];
    const float* prm_g = (const float*)d_in[3];
    const float* prm_o = (const float*)d_in[4];
    float* out = (float*)d_out;

    // 8192 warps: block = 4 quarters of one b-pair -> 2048 blocks
    qlstm_kernel<<<2048, 128>>>(inp, prm_f, prm_i, prm_g, prm_o, out);
}